// round 15
// baseline (speedup 1.0000x reference)
#include <cuda_runtime.h>
#include <math.h>
#include <stdint.h>

#define NROWS 32768
#define DDIM  1024
#define PDIM  256
#define NSEC  4
#define NCODE 1024
#define SECD  64

// ---------------- scratch (device globals, no allocation) ----------------
__device__ float g_P[NROWS * PDIM];         // projected  [N,P]
__device__ float g_Q[NROWS * PDIM];         // straight-through quantized [N,P]
__device__ float g_rowsum[NROWS];           // per-row squared recon error
__device__ float g_cov[PDIM * PDIM];        // P^T P accumulator
__device__ float g_cnorm[NSEC * NCODE];     // |c|^2 per code
__device__ float g_sx[NSEC * NROWS];        // |x_sec|^2 per (sec,row)
__device__ unsigned long long g_amin[NSEC * NROWS];  // packed (key, idx)
__device__ float g_l2sum;
__device__ float g_covsum;
__device__ float g_pca_loss;

// orderable key for total-order float compare via unsigned ints
__device__ __forceinline__ unsigned int fkey(float f) {
    unsigned int u = __float_as_uint(f);
    return (u & 0x80000000u) ? ~u : (u | 0x80000000u);
}

// ---------------- init ----------------
__global__ void k_zero() {
    int i = blockIdx.x * blockDim.x + threadIdx.x;
    if (i < NSEC * NROWS) g_amin[i] = 0xFFFFFFFFFFFFFFFFull;
    if (i < PDIM * PDIM)  g_cov[i] = 0.0f;
    if (i < NROWS)        g_rowsum[i] = 0.0f;
    if (i == 0) { g_l2sum = 0.0f; g_covsum = 0.0f; }
}

// |c|^2 per code — 8 accumulators (k mod 8) + pairwise tree combine
__global__ void k_cnorm(const float* __restrict__ cb) {
    int w = blockIdx.x * blockDim.x + threadIdx.x;
    if (w >= NSEC * NCODE) return;
    const float* p = cb + (size_t)w * SECD;
    float a[8] = {};
    for (int k = 0; k < SECD; k += 8) {
        #pragma unroll
        for (int j = 0; j < 8; j++) {
            float v = p[k + j];
            a[j] = __fadd_rn(a[j], __fmul_rn(v, v));
        }
    }
    float s01 = __fadd_rn(a[0], a[1]), s23 = __fadd_rn(a[2], a[3]);
    float s45 = __fadd_rn(a[4], a[5]), s67 = __fadd_rn(a[6], a[7]);
    g_cnorm[w] = __fadd_rn(__fadd_rn(s01, s23), __fadd_rn(s45, s67));
}

// |x_sec|^2 per (sec,row) — 8 accumulators (k mod 8) + pairwise tree combine
__global__ void k_sumx2() {
    int e = blockIdx.x * blockDim.x + threadIdx.x;
    if (e >= NSEC * NROWS) return;
    int s = e >> 15;            // e / NROWS
    int r = e & (NROWS - 1);    // e % NROWS
    const float* x = g_P + (size_t)r * PDIM + s * SECD;
    float a[8] = {};
    for (int k = 0; k < SECD; k += 8) {
        #pragma unroll
        for (int j = 0; j < 8; j++) {
            float v = x[k + j];
            a[j] = __fadd_rn(a[j], __fmul_rn(v, v));
        }
    }
    float s01 = __fadd_rn(a[0], a[1]), s23 = __fadd_rn(a[2], a[3]);
    float s45 = __fadd_rn(a[4], a[5]), s67 = __fadd_rn(a[6], a[7]);
    g_sx[e] = __fadd_rn(__fadd_rn(s01, s23), __fadd_rn(s45, s67));
}

// ---------------- GEMM 1: P = (X + bias) @ W   [N,D]x[D,P] ----------------
__global__ __launch_bounds__(256) void k_gemm_proj(
    const float* __restrict__ X, const float* __restrict__ W,
    const float* __restrict__ bias) {
    __shared__ float As[16][64];
    __shared__ float Bs[16][64];
    const int m0 = blockIdx.y * 64, n0 = blockIdx.x * 64;
    const int tid = threadIdx.x;
    const int ty = tid >> 4, tx = tid & 15;
    const int arow = tid >> 2, akg = (tid & 3) * 4;
    const int brow = tid >> 4, bng = (tid & 15) * 4;
    float acc[4][4] = {};
    for (int k0 = 0; k0 < DDIM; k0 += 16) {
        float4 a  = *(const float4*)(X + (size_t)(m0 + arow) * DDIM + k0 + akg);
        float4 pb = *(const float4*)(bias + k0 + akg);
        As[akg + 0][arow] = __fadd_rn(a.x, pb.x);
        As[akg + 1][arow] = __fadd_rn(a.y, pb.y);
        As[akg + 2][arow] = __fadd_rn(a.z, pb.z);
        As[akg + 3][arow] = __fadd_rn(a.w, pb.w);
        *(float4*)&Bs[brow][bng] =
            *(const float4*)(W + (size_t)(k0 + brow) * PDIM + n0 + bng);
        __syncthreads();
        #pragma unroll
        for (int k = 0; k < 16; k++) {
            float4 ra = *(const float4*)&As[k][ty * 4];
            float4 rb = *(const float4*)&Bs[k][tx * 4];
            float aa[4] = {ra.x, ra.y, ra.z, ra.w};
            float bb[4] = {rb.x, rb.y, rb.z, rb.w};
            #pragma unroll
            for (int i = 0; i < 4; i++)
                #pragma unroll
                for (int j = 0; j < 4; j++)
                    acc[i][j] = __fmaf_rn(aa[i], bb[j], acc[i][j]);
        }
        __syncthreads();
    }
    #pragma unroll
    for (int i = 0; i < 4; i++) {
        float4 v = make_float4(acc[i][0], acc[i][1], acc[i][2], acc[i][3]);
        *(float4*)(g_P + (size_t)(m0 + ty * 4 + i) * PDIM + n0 + tx * 4) = v;
    }
}

// ---- GEMM 2 (fused): U = P@W^T - bias; accumulate ||X - U||^2 per row ----
__global__ __launch_bounds__(256) void k_gemm_recon(
    const float* __restrict__ X, const float* __restrict__ W,
    const float* __restrict__ bias) {
    __shared__ float As[16][64];
    __shared__ float Bs[16][64];
    __shared__ float red[64][17];
    const int m0 = blockIdx.y * 64, d0 = blockIdx.x * 64;
    const int tid = threadIdx.x;
    const int ty = tid >> 4, tx = tid & 15;
    const int arow = tid >> 2, akg = (tid & 3) * 4;
    float acc[4][4] = {};
    for (int k0 = 0; k0 < PDIM; k0 += 16) {
        float4 a = *(const float4*)(g_P + (size_t)(m0 + arow) * PDIM + k0 + akg);
        As[akg + 0][arow] = a.x;
        As[akg + 1][arow] = a.y;
        As[akg + 2][arow] = a.z;
        As[akg + 3][arow] = a.w;
        float4 b = *(const float4*)(W + (size_t)(d0 + arow) * PDIM + k0 + akg);
        Bs[akg + 0][arow] = b.x;
        Bs[akg + 1][arow] = b.y;
        Bs[akg + 2][arow] = b.z;
        Bs[akg + 3][arow] = b.w;
        __syncthreads();
        #pragma unroll
        for (int k = 0; k < 16; k++) {
            float4 ra = *(const float4*)&As[k][ty * 4];
            float4 rb = *(const float4*)&Bs[k][tx * 4];
            float aa[4] = {ra.x, ra.y, ra.z, ra.w};
            float bb[4] = {rb.x, rb.y, rb.z, rb.w};
            #pragma unroll
            for (int i = 0; i < 4; i++)
                #pragma unroll
                for (int j = 0; j < 4; j++)
                    acc[i][j] = __fmaf_rn(aa[i], bb[j], acc[i][j]);
        }
        __syncthreads();
    }
    float4 b4 = *(const float4*)(bias + d0 + tx * 4);
    float bb[4] = {b4.x, b4.y, b4.z, b4.w};
    #pragma unroll
    for (int i = 0; i < 4; i++) {
        float4 x4 = *(const float4*)(X + (size_t)(m0 + ty * 4 + i) * DDIM + d0 + tx * 4);
        float xx[4] = {x4.x, x4.y, x4.z, x4.w};
        float part = 0.0f;
        #pragma unroll
        for (int j = 0; j < 4; j++) {
            float diff = xx[j] - (acc[i][j] - bb[j]);
            part += diff * diff;
        }
        red[ty * 4 + i][tx] = part;
    }
    __syncthreads();
    if (tid < 64) {
        float s = 0.0f;
        #pragma unroll
        for (int x = 0; x < 16; x++) s += red[tid][x];
        atomicAdd(&g_rowsum[m0 + tid], s);
    }
}

// ---------------- cov = P^T @ P (split-K, atomic accumulate) ----------------
__global__ __launch_bounds__(256) void k_cov() {
    __shared__ float Ai[16][64];
    __shared__ float Aj[16][64];
    const int i0 = blockIdx.x * 64, j0 = blockIdx.y * 64;
    const int mbase = blockIdx.z * 2048;
    const int tid = threadIdx.x;
    const int ty = tid >> 4, tx = tid & 15;
    const int mrow = tid >> 4, cg = (tid & 15) * 4;
    float acc[4][4] = {};
    for (int m0 = mbase; m0 < mbase + 2048; m0 += 16) {
        *(float4*)&Ai[mrow][cg] = *(const float4*)(g_P + (size_t)(m0 + mrow) * PDIM + i0 + cg);
        *(float4*)&Aj[mrow][cg] = *(const float4*)(g_P + (size_t)(m0 + mrow) * PDIM + j0 + cg);
        __syncthreads();
        #pragma unroll
        for (int k = 0; k < 16; k++) {
            float4 ra = *(const float4*)&Ai[k][ty * 4];
            float4 rb = *(const float4*)&Aj[k][tx * 4];
            float aa[4] = {ra.x, ra.y, ra.z, ra.w};
            float bb[4] = {rb.x, rb.y, rb.z, rb.w};
            #pragma unroll
            for (int i = 0; i < 4; i++)
                #pragma unroll
                for (int j = 0; j < 4; j++)
                    acc[i][j] = __fmaf_rn(aa[i], bb[j], acc[i][j]);
        }
        __syncthreads();
    }
    #pragma unroll
    for (int i = 0; i < 4; i++)
        #pragma unroll
        for (int j = 0; j < 4; j++)
            atomicAdd(&g_cov[(size_t)(i0 + ty * 4 + i) * PDIM + j0 + tx * 4 + j], acc[i][j]);
}

// ---------------- loss reductions ----------------
__global__ void k_l2reduce() {
    int i = blockIdx.x * blockDim.x + threadIdx.x;
    float v = (i < NROWS) ? sqrtf(g_rowsum[i]) : 0.0f;
    #pragma unroll
    for (int o = 16; o > 0; o >>= 1) v += __shfl_down_sync(0xFFFFFFFFu, v, o);
    __shared__ float w[8];
    if ((threadIdx.x & 31) == 0) w[threadIdx.x >> 5] = v;
    __syncthreads();
    if (threadIdx.x == 0) {
        float s = 0.0f;
        for (int q = 0; q < 8; q++) s += w[q];
        atomicAdd(&g_l2sum, s);
    }
}

__global__ void k_covloss() {
    int i = blockIdx.x * blockDim.x + threadIdx.x;
    float v = 0.0f;
    if (i < PDIM * PDIM) {
        int r = i >> 8, c = i & 255;
        v = g_cov[i] * (1.0f / NROWS) - (r == c ? 1.0f : 0.0f);
        v = v * v;
    }
    #pragma unroll
    for (int o = 16; o > 0; o >>= 1) v += __shfl_down_sync(0xFFFFFFFFu, v, o);
    __shared__ float w[8];
    if ((threadIdx.x & 31) == 0) w[threadIdx.x >> 5] = v;
    __syncthreads();
    if (threadIdx.x == 0) {
        float s = 0.0f;
        for (int q = 0; q < 8; q++) s += w[q];
        atomicAdd(&g_covsum, s);
    }
}

__global__ void k_finalize() {
    g_pca_loss = g_l2sum * (1.0f / NROWS) + g_covsum * (1.0f / (PDIM * PDIM));
}

// ------- VQ scores + argmin (LOW-index tie-break) via packed atomicMin -------
// t via FOUR accumulators (k mod 4) combined pairwise: rn(rn(A0+A1)+rn(A2+A3))
// d = rn(rn(sx - 2t) + cn)
__global__ __launch_bounds__(256) void k_vqscore(const float* __restrict__ cb) {
    __shared__ float As[16][64];
    __shared__ float Bs[16][64];
    __shared__ unsigned long long red[64][17];
    const int s = blockIdx.z;
    const int m0 = blockIdx.y * 64, c0 = blockIdx.x * 64;
    const int tid = threadIdx.x;
    const int ty = tid >> 4, tx = tid & 15;
    const int arow = tid >> 2, akg = (tid & 3) * 4;
    float acc0[4][4] = {};
    float acc1[4][4] = {};
    float acc2[4][4] = {};
    float acc3[4][4] = {};
    const float* cbs = cb + (size_t)s * NCODE * SECD;
    #pragma unroll
    for (int k0 = 0; k0 < SECD; k0 += 16) {
        float4 a = *(const float4*)(g_P + (size_t)(m0 + arow) * PDIM + s * SECD + k0 + akg);
        As[akg + 0][arow] = a.x;
        As[akg + 1][arow] = a.y;
        As[akg + 2][arow] = a.z;
        As[akg + 3][arow] = a.w;
        float4 b = *(const float4*)(cbs + (size_t)(c0 + arow) * SECD + k0 + akg);
        Bs[akg + 0][arow] = b.x;
        Bs[akg + 1][arow] = b.y;
        Bs[akg + 2][arow] = b.z;
        Bs[akg + 3][arow] = b.w;
        __syncthreads();
        #pragma unroll
        for (int k = 0; k < 16; k++) {
            float (*acc)[4] = ((k & 3) == 0) ? acc0 :
                              ((k & 3) == 1) ? acc1 :
                              ((k & 3) == 2) ? acc2 : acc3;
            float4 ra = *(const float4*)&As[k][ty * 4];
            float4 rb = *(const float4*)&Bs[k][tx * 4];
            float aa[4] = {ra.x, ra.y, ra.z, ra.w};
            float bb[4] = {rb.x, rb.y, rb.z, rb.w};
            #pragma unroll
            for (int i = 0; i < 4; i++)
                #pragma unroll
                for (int j = 0; j < 4; j++)
                    acc[i][j] = __fmaf_rn(aa[i], bb[j], acc[i][j]);
        }
        __syncthreads();
    }
    float cn[4];
    #pragma unroll
    for (int j = 0; j < 4; j++) cn[j] = g_cnorm[s * NCODE + c0 + tx * 4 + j];
    #pragma unroll
    for (int i = 0; i < 4; i++) {
        float sx = g_sx[s * NROWS + m0 + ty * 4 + i];
        unsigned long long best = 0xFFFFFFFFFFFFFFFFull;
        #pragma unroll
        for (int j = 0; j < 4; j++) {
            float t = __fadd_rn(__fadd_rn(acc0[i][j], acc1[i][j]),
                                __fadd_rn(acc2[i][j], acc3[i][j]));
            float sc = __fadd_rn(__fsub_rn(sx, __fmul_rn(2.0f, t)), cn[j]);
            unsigned long long p =
                ((unsigned long long)fkey(sc) << 32) | (unsigned)(c0 + tx * 4 + j);
            if (p < best) best = p;
        }
        red[ty * 4 + i][tx] = best;
    }
    __syncthreads();
    if (tid < 64) {
        unsigned long long best = red[tid][0];
        #pragma unroll
        for (int x = 1; x < 16; x++) if (red[tid][x] < best) best = red[tid][x];
        atomicMin(&g_amin[(size_t)s * NROWS + m0 + tid], best);
    }
}

// ------- gather quantized sections with straight-through rounding -------
__global__ void k_gather(const float* __restrict__ cb) {
    int e = blockIdx.x * blockDim.x + threadIdx.x;   // over NROWS*PDIM
    int n = e >> 8, p = e & 255, s = p >> 6, j = p & 63;
    int idx = (int)(unsigned)(g_amin[(size_t)s * NROWS + n] & 0xFFFFFFFFull);
    float q = cb[(size_t)s * NCODE * SECD + (size_t)idx * SECD + j];
    float x = g_P[e];
    g_Q[e] = __fadd_rn(x, __fsub_rn(q, x));
}

// ---------------- GEMM 5: out = Q_st @ W^T - bias ----------------
__global__ __launch_bounds__(256) void k_gemm_out(
    const float* __restrict__ W, const float* __restrict__ bias,
    float* __restrict__ out) {
    __shared__ float As[16][64];
    __shared__ float Bs[16][64];
    const int m0 = blockIdx.y * 64, d0 = blockIdx.x * 64;
    const int tid = threadIdx.x;
    const int ty = tid >> 4, tx = tid & 15;
    const int arow = tid >> 2, akg = (tid & 3) * 4;
    float acc[4][4] = {};
    for (int k0 = 0; k0 < PDIM; k0 += 16) {
        float4 a = *(const float4*)(g_Q + (size_t)(m0 + arow) * PDIM + k0 + akg);
        As[akg + 0][arow] = a.x;
        As[akg + 1][arow] = a.y;
        As[akg + 2][arow] = a.z;
        As[akg + 3][arow] = a.w;
        float4 b = *(const float4*)(W + (size_t)(d0 + arow) * PDIM + k0 + akg);
        Bs[akg + 0][arow] = b.x;
        Bs[akg + 1][arow] = b.y;
        Bs[akg + 2][arow] = b.z;
        Bs[akg + 3][arow] = b.w;
        __syncthreads();
        #pragma unroll
        for (int k = 0; k < 16; k++) {
            float4 ra = *(const float4*)&As[k][ty * 4];
            float4 rb = *(const float4*)&Bs[k][tx * 4];
            float aa[4] = {ra.x, ra.y, ra.z, ra.w};
            float bb[4] = {rb.x, rb.y, rb.z, rb.w};
            #pragma unroll
            for (int i = 0; i < 4; i++)
                #pragma unroll
                for (int j = 0; j < 4; j++)
                    acc[i][j] = __fmaf_rn(aa[i], bb[j], acc[i][j]);
        }
        __syncthreads();
    }
    float4 b4 = *(const float4*)(bias + d0 + tx * 4);
    #pragma unroll
    for (int i = 0; i < 4; i++) {
        float4 v = make_float4(acc[i][0] - b4.x, acc[i][1] - b4.y,
                               acc[i][2] - b4.z, acc[i][3] - b4.w);
        *(float4*)(out + (size_t)(m0 + ty * 4 + i) * DDIM + d0 + tx * 4) = v;
    }
}

// ------------- quantization loss (raw q vs fp32 P) -------------
__global__ void k_qloss(const float* __restrict__ cb, float* __restrict__ out_ql) {
    int e = blockIdx.x * blockDim.x + threadIdx.x;   // over NROWS*SECD
    int n = e >> 6, j = e & 63;
    float sum = 0.0f;
    #pragma unroll
    for (int s = 0; s < NSEC; s++) {
        int idx = (int)(unsigned)(g_amin[(size_t)s * NROWS + n] & 0xFFFFFFFFull);
        float q = cb[(size_t)s * NCODE * SECD + (size_t)idx * SECD + j];
        float x = g_P[(size_t)n * PDIM + s * SECD + j];
        float d = __fsub_rn(q, x);
        sum += d * d;
    }
    out_ql[e] = 0.25f * sum + g_pca_loss;
}

// ---------------- misc outputs: nn_idx, codebook copy, counts ----------------
__global__ void k_misc(const float* __restrict__ cb, float* __restrict__ out_cb,
                       float* __restrict__ out_nn, float* __restrict__ out_cc) {
    int e = blockIdx.x * blockDim.x + threadIdx.x;
    if (e < NSEC * NCODE * SECD) out_cb[e] = cb[e];
    if (e < NSEC * NROWS)
        out_nn[e] = (float)(unsigned)(g_amin[e] & 0xFFFFFFFFull);
    if (e < NSEC * NCODE) out_cc[e] = 1.0f;
}

// ---------------- launcher ----------------
extern "C" void kernel_launch(void* const* d_in, const int* in_sizes, int n_in,
                              void* d_out, int out_size) {
    const float* X    = (const float*)d_in[0];   // [32768,1024]
    const float* W    = (const float*)d_in[1];   // [1024,256]
    const float* bias = (const float*)d_in[2];   // [1,1024]
    const float* cb   = (const float*)d_in[3];   // [4,1024,64]
    float* out = (float*)d_out;

    float* out_q  = out;                          // 33554432
    float* out_ql = out_q + 33554432;             // 2097152
    float* out_nn = out_ql + 2097152;             // 131072
    float* out_cb = out_nn + 131072;              // 262144
    float* out_cc = out_cb + 262144;              // 4096

    k_zero<<<512, 256>>>();
    k_cnorm<<<NSEC * NCODE / 256, 256>>>(cb);
    k_gemm_proj<<<dim3(PDIM / 64, NROWS / 64), 256>>>(X, W, bias);
    k_sumx2<<<NSEC * NROWS / 256, 256>>>();
    k_gemm_recon<<<dim3(DDIM / 64, NROWS / 64), 256>>>(X, W, bias);
    k_cov<<<dim3(4, 4, 16), 256>>>();
    k_l2reduce<<<NROWS / 256, 256>>>();
    k_covloss<<<PDIM * PDIM / 256, 256>>>();
    k_finalize<<<1, 1>>>();
    k_vqscore<<<dim3(NCODE / 64, NROWS / 64, NSEC), 256>>>(cb);
    k_gather<<<NROWS * PDIM / 256, 256>>>(cb);
    k_gemm_out<<<dim3(DDIM / 64, NROWS / 64), 256>>>(W, bias, out_q);
    k_qloss<<<NROWS * SECD / 256, 256>>>(cb, out_ql);
    k_misc<<<NSEC * NCODE * SECD / 256, 256>>>(cb, out_cb, out_nn, out_cc);
}

// round 16
// speedup vs baseline: 1.9396x; 1.9396x over previous
#include <cuda_runtime.h>
#include <math.h>
#include <stdint.h>

#define NROWS 32768
#define DDIM  1024
#define PDIM  256
#define NSEC  4
#define NCODE 1024
#define SECD  64

// ---------------- scratch (device globals, no allocation) ----------------
__device__ float g_P[NROWS * PDIM];         // projected  [N,P]
__device__ float g_Q[NROWS * PDIM];         // straight-through quantized [N,P]
__device__ float g_rowsum[NROWS];           // per-row squared recon error
__device__ float g_cov[PDIM * PDIM];        // P^T P accumulator
__device__ float g_cnorm[NSEC * NCODE];     // |c|^2 per code
__device__ float g_sx[NSEC * NROWS];        // |x_sec|^2 per (sec,row)
__device__ unsigned long long g_amin[NSEC * NROWS];  // packed (key, idx)
__device__ float g_l2sum;
__device__ float g_covsum;
__device__ float g_pca_loss;

__device__ __forceinline__ unsigned int fkey(float f) {
    unsigned int u = __float_as_uint(f);
    return (u & 0x80000000u) ? ~u : (u | 0x80000000u);
}

// ---------------- init ----------------
__global__ void k_zero() {
    int i = blockIdx.x * blockDim.x + threadIdx.x;
    if (i < NSEC * NROWS) g_amin[i] = 0xFFFFFFFFFFFFFFFFull;
    if (i < PDIM * PDIM)  g_cov[i] = 0.0f;
    if (i < NROWS)        g_rowsum[i] = 0.0f;
    if (i == 0) { g_l2sum = 0.0f; g_covsum = 0.0f; }
}

// |c|^2 — 8 accumulators (k mod 8) + pairwise tree (SACRED chain; float4 loads)
__global__ void k_cnorm(const float* __restrict__ cb) {
    int w = blockIdx.x * blockDim.x + threadIdx.x;
    if (w >= NSEC * NCODE) return;
    const float* p = cb + (size_t)w * SECD;
    float a[8] = {};
    for (int k = 0; k < SECD; k += 8) {
        float4 v0 = *(const float4*)(p + k);
        float4 v1 = *(const float4*)(p + k + 4);
        a[0] = __fadd_rn(a[0], __fmul_rn(v0.x, v0.x));
        a[1] = __fadd_rn(a[1], __fmul_rn(v0.y, v0.y));
        a[2] = __fadd_rn(a[2], __fmul_rn(v0.z, v0.z));
        a[3] = __fadd_rn(a[3], __fmul_rn(v0.w, v0.w));
        a[4] = __fadd_rn(a[4], __fmul_rn(v1.x, v1.x));
        a[5] = __fadd_rn(a[5], __fmul_rn(v1.y, v1.y));
        a[6] = __fadd_rn(a[6], __fmul_rn(v1.z, v1.z));
        a[7] = __fadd_rn(a[7], __fmul_rn(v1.w, v1.w));
    }
    float s01 = __fadd_rn(a[0], a[1]), s23 = __fadd_rn(a[2], a[3]);
    float s45 = __fadd_rn(a[4], a[5]), s67 = __fadd_rn(a[6], a[7]);
    g_cnorm[w] = __fadd_rn(__fadd_rn(s01, s23), __fadd_rn(s45, s67));
}

// |x_sec|^2 — 8 accumulators + pairwise tree (SACRED chain; float4 loads)
__global__ void k_sumx2() {
    int e = blockIdx.x * blockDim.x + threadIdx.x;
    if (e >= NSEC * NROWS) return;
    int s = e >> 15;
    int r = e & (NROWS - 1);
    const float* x = g_P + (size_t)r * PDIM + s * SECD;
    float a[8] = {};
    for (int k = 0; k < SECD; k += 8) {
        float4 v0 = *(const float4*)(x + k);
        float4 v1 = *(const float4*)(x + k + 4);
        a[0] = __fadd_rn(a[0], __fmul_rn(v0.x, v0.x));
        a[1] = __fadd_rn(a[1], __fmul_rn(v0.y, v0.y));
        a[2] = __fadd_rn(a[2], __fmul_rn(v0.z, v0.z));
        a[3] = __fadd_rn(a[3], __fmul_rn(v0.w, v0.w));
        a[4] = __fadd_rn(a[4], __fmul_rn(v1.x, v1.x));
        a[5] = __fadd_rn(a[5], __fmul_rn(v1.y, v1.y));
        a[6] = __fadd_rn(a[6], __fmul_rn(v1.z, v1.z));
        a[7] = __fadd_rn(a[7], __fmul_rn(v1.w, v1.w));
    }
    float s01 = __fadd_rn(a[0], a[1]), s23 = __fadd_rn(a[2], a[3]);
    float s45 = __fadd_rn(a[4], a[5]), s67 = __fadd_rn(a[6], a[7]);
    g_sx[e] = __fadd_rn(__fadd_rn(s01, s23), __fadd_rn(s45, s67));
}

// ====== GEMM 1: P = (X + bias) @ W — 128x128 tile, 8x8 microtile ======
// per-element chain: single acc, ascending k (bit-identical to R15)
__global__ __launch_bounds__(256) void k_gemm_proj(
    const float* __restrict__ X, const float* __restrict__ W,
    const float* __restrict__ bias) {
    __shared__ float As[16][128];
    __shared__ float Bs[16][128];
    const int m0 = blockIdx.y * 128, n0 = blockIdx.x * 128;
    const int tid = threadIdx.x;
    const int ty = tid >> 4, tx = tid & 15;
    float acc[2][2][4][4] = {};
    for (int k0 = 0; k0 < DDIM; k0 += 16) {
        // load A tile (128 rows x 16 k) with bias, transposed into As[k][m]
        #pragma unroll
        for (int q = 0; q < 2; q++) {
            int t = tid * 2 + q;
            int r = t >> 2, cg = (t & 3) * 4;
            float4 a = *(const float4*)(X + (size_t)(m0 + r) * DDIM + k0 + cg);
            float4 pb = *(const float4*)(bias + k0 + cg);
            As[cg + 0][r] = __fadd_rn(a.x, pb.x);
            As[cg + 1][r] = __fadd_rn(a.y, pb.y);
            As[cg + 2][r] = __fadd_rn(a.z, pb.z);
            As[cg + 3][r] = __fadd_rn(a.w, pb.w);
        }
        // load B tile (16 k x 128 n) direct
        #pragma unroll
        for (int q = 0; q < 2; q++) {
            int t = tid * 2 + q;
            int r = t >> 5, cg = (t & 31) * 4;
            *(float4*)&Bs[r][cg] =
                *(const float4*)(W + (size_t)(k0 + r) * PDIM + n0 + cg);
        }
        __syncthreads();
        #pragma unroll
        for (int k = 0; k < 16; k++) {
            float4 ra0 = *(const float4*)&As[k][ty * 4];
            float4 ra1 = *(const float4*)&As[k][64 + ty * 4];
            float4 rb0 = *(const float4*)&Bs[k][tx * 4];
            float4 rb1 = *(const float4*)&Bs[k][64 + tx * 4];
            float aa[2][4] = {{ra0.x, ra0.y, ra0.z, ra0.w},
                              {ra1.x, ra1.y, ra1.z, ra1.w}};
            float bb[2][4] = {{rb0.x, rb0.y, rb0.z, rb0.w},
                              {rb1.x, rb1.y, rb1.z, rb1.w}};
            #pragma unroll
            for (int p = 0; p < 2; p++)
                #pragma unroll
                for (int q2 = 0; q2 < 2; q2++)
                    #pragma unroll
                    for (int i = 0; i < 4; i++)
                        #pragma unroll
                        for (int j = 0; j < 4; j++)
                            acc[p][q2][i][j] =
                                __fmaf_rn(aa[p][i], bb[q2][j], acc[p][q2][i][j]);
        }
        __syncthreads();
    }
    #pragma unroll
    for (int p = 0; p < 2; p++)
        #pragma unroll
        for (int i = 0; i < 4; i++) {
            int row = m0 + p * 64 + ty * 4 + i;
            #pragma unroll
            for (int q2 = 0; q2 < 2; q2++) {
                float4 v = make_float4(acc[p][q2][i][0], acc[p][q2][i][1],
                                       acc[p][q2][i][2], acc[p][q2][i][3]);
                *(float4*)(g_P + (size_t)row * PDIM + n0 + q2 * 64 + tx * 4) = v;
            }
        }
}

// == GEMM 2 (fused): U = P@W^T - bias; accumulate ||X-U||^2 — 128x128 tile ==
__global__ __launch_bounds__(256) void k_gemm_recon(
    const float* __restrict__ X, const float* __restrict__ W,
    const float* __restrict__ bias) {
    __shared__ float As[16][128];
    __shared__ float Bs[16][128];
    __shared__ float red[128][17];
    const int m0 = blockIdx.y * 128, d0 = blockIdx.x * 128;
    const int tid = threadIdx.x;
    const int ty = tid >> 4, tx = tid & 15;
    float acc[2][2][4][4] = {};
    for (int k0 = 0; k0 < PDIM; k0 += 16) {
        #pragma unroll
        for (int q = 0; q < 2; q++) {
            int t = tid * 2 + q;
            int r = t >> 2, cg = (t & 3) * 4;
            float4 a = *(const float4*)(g_P + (size_t)(m0 + r) * PDIM + k0 + cg);
            As[cg + 0][r] = a.x;
            As[cg + 1][r] = a.y;
            As[cg + 2][r] = a.z;
            As[cg + 3][r] = a.w;
            // B = W^T: Bs[k][d] = W[d][k]
            float4 b = *(const float4*)(W + (size_t)(d0 + r) * PDIM + k0 + cg);
            Bs[cg + 0][r] = b.x;
            Bs[cg + 1][r] = b.y;
            Bs[cg + 2][r] = b.z;
            Bs[cg + 3][r] = b.w;
        }
        __syncthreads();
        #pragma unroll
        for (int k = 0; k < 16; k++) {
            float4 ra0 = *(const float4*)&As[k][ty * 4];
            float4 ra1 = *(const float4*)&As[k][64 + ty * 4];
            float4 rb0 = *(const float4*)&Bs[k][tx * 4];
            float4 rb1 = *(const float4*)&Bs[k][64 + tx * 4];
            float aa[2][4] = {{ra0.x, ra0.y, ra0.z, ra0.w},
                              {ra1.x, ra1.y, ra1.z, ra1.w}};
            float bb[2][4] = {{rb0.x, rb0.y, rb0.z, rb0.w},
                              {rb1.x, rb1.y, rb1.z, rb1.w}};
            #pragma unroll
            for (int p = 0; p < 2; p++)
                #pragma unroll
                for (int q2 = 0; q2 < 2; q2++)
                    #pragma unroll
                    for (int i = 0; i < 4; i++)
                        #pragma unroll
                        for (int j = 0; j < 4; j++)
                            acc[p][q2][i][j] =
                                __fmaf_rn(aa[p][i], bb[q2][j], acc[p][q2][i][j]);
        }
        __syncthreads();
    }
    // epilogue: diff vs X, per-row partial sums
    #pragma unroll
    for (int p = 0; p < 2; p++)
        #pragma unroll
        for (int i = 0; i < 4; i++) {
            int rl = p * 64 + ty * 4 + i;
            int row = m0 + rl;
            float part = 0.0f;
            #pragma unroll
            for (int q2 = 0; q2 < 2; q2++) {
                int dg = d0 + q2 * 64 + tx * 4;
                float4 b4 = *(const float4*)(bias + dg);
                float4 x4 = *(const float4*)(X + (size_t)row * DDIM + dg);
                float bb[4] = {b4.x, b4.y, b4.z, b4.w};
                float xx[4] = {x4.x, x4.y, x4.z, x4.w};
                #pragma unroll
                for (int j = 0; j < 4; j++) {
                    float diff = xx[j] - (acc[p][q2][i][j] - bb[j]);
                    part += diff * diff;
                }
            }
            red[rl][tx] = part;
        }
    __syncthreads();
    if (tid < 128) {
        float s = 0.0f;
        #pragma unroll
        for (int x = 0; x < 16; x++) s += red[tid][x];
        atomicAdd(&g_rowsum[m0 + tid], s);
    }
}

// ---------------- cov = P^T @ P (split-K, atomic accumulate) ----------------
__global__ __launch_bounds__(256) void k_cov() {
    __shared__ float Ai[16][64];
    __shared__ float Aj[16][64];
    const int i0 = blockIdx.x * 64, j0 = blockIdx.y * 64;
    const int mbase = blockIdx.z * 2048;
    const int tid = threadIdx.x;
    const int ty = tid >> 4, tx = tid & 15;
    const int mrow = tid >> 4, cg = (tid & 15) * 4;
    float acc[4][4] = {};
    for (int m0 = mbase; m0 < mbase + 2048; m0 += 16) {
        *(float4*)&Ai[mrow][cg] = *(const float4*)(g_P + (size_t)(m0 + mrow) * PDIM + i0 + cg);
        *(float4*)&Aj[mrow][cg] = *(const float4*)(g_P + (size_t)(m0 + mrow) * PDIM + j0 + cg);
        __syncthreads();
        #pragma unroll
        for (int k = 0; k < 16; k++) {
            float4 ra = *(const float4*)&Ai[k][ty * 4];
            float4 rb = *(const float4*)&Aj[k][tx * 4];
            float aa[4] = {ra.x, ra.y, ra.z, ra.w};
            float bb[4] = {rb.x, rb.y, rb.z, rb.w};
            #pragma unroll
            for (int i = 0; i < 4; i++)
                #pragma unroll
                for (int j = 0; j < 4; j++)
                    acc[i][j] = __fmaf_rn(aa[i], bb[j], acc[i][j]);
        }
        __syncthreads();
    }
    #pragma unroll
    for (int i = 0; i < 4; i++)
        #pragma unroll
        for (int j = 0; j < 4; j++)
            atomicAdd(&g_cov[(size_t)(i0 + ty * 4 + i) * PDIM + j0 + tx * 4 + j], acc[i][j]);
}

// ---------------- loss reductions ----------------
__global__ void k_l2reduce() {
    int i = blockIdx.x * blockDim.x + threadIdx.x;
    float v = (i < NROWS) ? sqrtf(g_rowsum[i]) : 0.0f;
    #pragma unroll
    for (int o = 16; o > 0; o >>= 1) v += __shfl_down_sync(0xFFFFFFFFu, v, o);
    __shared__ float w[8];
    if ((threadIdx.x & 31) == 0) w[threadIdx.x >> 5] = v;
    __syncthreads();
    if (threadIdx.x == 0) {
        float s = 0.0f;
        for (int q = 0; q < 8; q++) s += w[q];
        atomicAdd(&g_l2sum, s);
    }
}

__global__ void k_covloss() {
    int i = blockIdx.x * blockDim.x + threadIdx.x;
    float v = 0.0f;
    if (i < PDIM * PDIM) {
        int r = i >> 8, c = i & 255;
        v = g_cov[i] * (1.0f / NROWS) - (r == c ? 1.0f : 0.0f);
        v = v * v;
    }
    #pragma unroll
    for (int o = 16; o > 0; o >>= 1) v += __shfl_down_sync(0xFFFFFFFFu, v, o);
    __shared__ float w[8];
    if ((threadIdx.x & 31) == 0) w[threadIdx.x >> 5] = v;
    __syncthreads();
    if (threadIdx.x == 0) {
        float s = 0.0f;
        for (int q = 0; q < 8; q++) s += w[q];
        atomicAdd(&g_covsum, s);
    }
}

__global__ void k_finalize() {
    g_pca_loss = g_l2sum * (1.0f / NROWS) + g_covsum * (1.0f / (PDIM * PDIM));
}

// ------- VQ scores + argmin — SACRED: unchanged from R15 passing kernel -------
__global__ __launch_bounds__(256) void k_vqscore(const float* __restrict__ cb) {
    __shared__ float As[16][64];
    __shared__ float Bs[16][64];
    __shared__ unsigned long long red[64][17];
    const int s = blockIdx.z;
    const int m0 = blockIdx.y * 64, c0 = blockIdx.x * 64;
    const int tid = threadIdx.x;
    const int ty = tid >> 4, tx = tid & 15;
    const int arow = tid >> 2, akg = (tid & 3) * 4;
    float acc0[4][4] = {};
    float acc1[4][4] = {};
    float acc2[4][4] = {};
    float acc3[4][4] = {};
    const float* cbs = cb + (size_t)s * NCODE * SECD;
    #pragma unroll
    for (int k0 = 0; k0 < SECD; k0 += 16) {
        float4 a = *(const float4*)(g_P + (size_t)(m0 + arow) * PDIM + s * SECD + k0 + akg);
        As[akg + 0][arow] = a.x;
        As[akg + 1][arow] = a.y;
        As[akg + 2][arow] = a.z;
        As[akg + 3][arow] = a.w;
        float4 b = *(const float4*)(cbs + (size_t)(c0 + arow) * SECD + k0 + akg);
        Bs[akg + 0][arow] = b.x;
        Bs[akg + 1][arow] = b.y;
        Bs[akg + 2][arow] = b.z;
        Bs[akg + 3][arow] = b.w;
        __syncthreads();
        #pragma unroll
        for (int k = 0; k < 16; k++) {
            float (*acc)[4] = ((k & 3) == 0) ? acc0 :
                              ((k & 3) == 1) ? acc1 :
                              ((k & 3) == 2) ? acc2 : acc3;
            float4 ra = *(const float4*)&As[k][ty * 4];
            float4 rb = *(const float4*)&Bs[k][tx * 4];
            float aa[4] = {ra.x, ra.y, ra.z, ra.w};
            float bb[4] = {rb.x, rb.y, rb.z, rb.w};
            #pragma unroll
            for (int i = 0; i < 4; i++)
                #pragma unroll
                for (int j = 0; j < 4; j++)
                    acc[i][j] = __fmaf_rn(aa[i], bb[j], acc[i][j]);
        }
        __syncthreads();
    }
    float cn[4];
    #pragma unroll
    for (int j = 0; j < 4; j++) cn[j] = g_cnorm[s * NCODE + c0 + tx * 4 + j];
    #pragma unroll
    for (int i = 0; i < 4; i++) {
        float sx = g_sx[s * NROWS + m0 + ty * 4 + i];
        unsigned long long best = 0xFFFFFFFFFFFFFFFFull;
        #pragma unroll
        for (int j = 0; j < 4; j++) {
            float t = __fadd_rn(__fadd_rn(acc0[i][j], acc1[i][j]),
                                __fadd_rn(acc2[i][j], acc3[i][j]));
            float sc = __fadd_rn(__fsub_rn(sx, __fmul_rn(2.0f, t)), cn[j]);
            unsigned long long p =
                ((unsigned long long)fkey(sc) << 32) | (unsigned)(c0 + tx * 4 + j);
            if (p < best) best = p;
        }
        red[ty * 4 + i][tx] = best;
    }
    __syncthreads();
    if (tid < 64) {
        unsigned long long best = red[tid][0];
        #pragma unroll
        for (int x = 1; x < 16; x++) if (red[tid][x] < best) best = red[tid][x];
        atomicMin(&g_amin[(size_t)s * NROWS + m0 + tid], best);
    }
}

// ------- gather quantized sections with straight-through rounding -------
__global__ void k_gather(const float* __restrict__ cb) {
    int e = blockIdx.x * blockDim.x + threadIdx.x;
    int n = e >> 8, p = e & 255, s = p >> 6, j = p & 63;
    int idx = (int)(unsigned)(g_amin[(size_t)s * NROWS + n] & 0xFFFFFFFFull);
    float q = cb[(size_t)s * NCODE * SECD + (size_t)idx * SECD + j];
    float x = g_P[e];
    g_Q[e] = __fadd_rn(x, __fsub_rn(q, x));
}

// ====== GEMM 5: out = Q_st @ W^T - bias — 128x128 tile, 8x8 microtile ======
__global__ __launch_bounds__(256) void k_gemm_out(
    const float* __restrict__ W, const float* __restrict__ bias,
    float* __restrict__ out) {
    __shared__ float As[16][128];
    __shared__ float Bs[16][128];
    const int m0 = blockIdx.y * 128, d0 = blockIdx.x * 128;
    const int tid = threadIdx.x;
    const int ty = tid >> 4, tx = tid & 15;
    float acc[2][2][4][4] = {};
    for (int k0 = 0; k0 < PDIM; k0 += 16) {
        #pragma unroll
        for (int q = 0; q < 2; q++) {
            int t = tid * 2 + q;
            int r = t >> 2, cg = (t & 3) * 4;
            float4 a = *(const float4*)(g_Q + (size_t)(m0 + r) * PDIM + k0 + cg);
            As[cg + 0][r] = a.x;
            As[cg + 1][r] = a.y;
            As[cg + 2][r] = a.z;
            As[cg + 3][r] = a.w;
            float4 b = *(const float4*)(W + (size_t)(d0 + r) * PDIM + k0 + cg);
            Bs[cg + 0][r] = b.x;
            Bs[cg + 1][r] = b.y;
            Bs[cg + 2][r] = b.z;
            Bs[cg + 3][r] = b.w;
        }
        __syncthreads();
        #pragma unroll
        for (int k = 0; k < 16; k++) {
            float4 ra0 = *(const float4*)&As[k][ty * 4];
            float4 ra1 = *(const float4*)&As[k][64 + ty * 4];
            float4 rb0 = *(const float4*)&Bs[k][tx * 4];
            float4 rb1 = *(const float4*)&Bs[k][64 + tx * 4];
            float aa[2][4] = {{ra0.x, ra0.y, ra0.z, ra0.w},
                              {ra1.x, ra1.y, ra1.z, ra1.w}};
            float bb[2][4] = {{rb0.x, rb0.y, rb0.z, rb0.w},
                              {rb1.x, rb1.y, rb1.z, rb1.w}};
            #pragma unroll
            for (int p = 0; p < 2; p++)
                #pragma unroll
                for (int q2 = 0; q2 < 2; q2++)
                    #pragma unroll
                    for (int i = 0; i < 4; i++)
                        #pragma unroll
                        for (int j = 0; j < 4; j++)
                            acc[p][q2][i][j] =
                                __fmaf_rn(aa[p][i], bb[q2][j], acc[p][q2][i][j]);
        }
        __syncthreads();
    }
    #pragma unroll
    for (int p = 0; p < 2; p++)
        #pragma unroll
        for (int i = 0; i < 4; i++) {
            int row = m0 + p * 64 + ty * 4 + i;
            #pragma unroll
            for (int q2 = 0; q2 < 2; q2++) {
                int dg = d0 + q2 * 64 + tx * 4;
                float4 b4 = *(const float4*)(bias + dg);
                float4 v = make_float4(acc[p][q2][i][0] - b4.x,
                                       acc[p][q2][i][1] - b4.y,
                                       acc[p][q2][i][2] - b4.z,
                                       acc[p][q2][i][3] - b4.w);
                *(float4*)(out + (size_t)row * DDIM + dg) = v;
            }
        }
}

// ------------- quantization loss (raw q vs fp32 P) -------------
__global__ void k_qloss(const float* __restrict__ cb, float* __restrict__ out_ql) {
    int e = blockIdx.x * blockDim.x + threadIdx.x;
    int n = e >> 6, j = e & 63;
    float sum = 0.0f;
    #pragma unroll
    for (int s = 0; s < NSEC; s++) {
        int idx = (int)(unsigned)(g_amin[(size_t)s * NROWS + n] & 0xFFFFFFFFull);
        float q = cb[(size_t)s * NCODE * SECD + (size_t)idx * SECD + j];
        float x = g_P[(size_t)n * PDIM + s * SECD + j];
        float d = __fsub_rn(q, x);
        sum += d * d;
    }
    out_ql[e] = 0.25f * sum + g_pca_loss;
}

// ---------------- misc outputs ----------------
__global__ void k_misc(const float* __restrict__ cb, float* __restrict__ out_cb,
                       float* __restrict__ out_nn, float* __restrict__ out_cc) {
    int e = blockIdx.x * blockDim.x + threadIdx.x;
    if (e < NSEC * NCODE * SECD) out_cb[e] = cb[e];
    if (e < NSEC * NROWS)
        out_nn[e] = (float)(unsigned)(g_amin[e] & 0xFFFFFFFFull);
    if (e < NSEC * NCODE) out_cc[e] = 1.0f;
}

// ---------------- launcher ----------------
extern "C" void kernel_launch(void* const* d_in, const int* in_sizes, int n_in,
                              void* d_out, int out_size) {
    const float* X    = (const float*)d_in[0];
    const float* W    = (const float*)d_in[1];
    const float* bias = (const float*)d_in[2];
    const float* cb   = (const float*)d_in[3];
    float* out = (float*)d_out;

    float* out_q  = out;                          // 33554432
    float* out_ql = out_q + 33554432;             // 2097152
    float* out_nn = out_ql + 2097152;             // 131072
    float* out_cb = out_nn + 131072;              // 262144
    float* out_cc = out_cb + 262144;              // 4096

    k_zero<<<512, 256>>>();
    k_cnorm<<<NSEC * NCODE / 256, 256>>>(cb);
    k_gemm_proj<<<dim3(PDIM / 128, NROWS / 128), 256>>>(X, W, bias);
    k_sumx2<<<NSEC * NROWS / 256, 256>>>();
    k_gemm_recon<<<dim3(DDIM / 128, NROWS / 128), 256>>>(X, W, bias);
    k_cov<<<dim3(4, 4, 16), 256>>>();
    k_l2reduce<<<NROWS / 256, 256>>>();
    k_covloss<<<PDIM * PDIM / 256, 256>>>();
    k_finalize<<<1, 1>>>();
    k_vqscore<<<dim3(NCODE / 64, NROWS / 64, NSEC), 256>>>(cb);
    k_gather<<<NROWS * PDIM / 256, 256>>>(cb);
    k_gemm_out<<<dim3(DDIM / 128, NROWS / 128), 256>>>(W, bias, out_q);
    k_qloss<<<NROWS * SECD / 256, 256>>>(cb, out_ql);
    k_misc<<<NSEC * NCODE * SECD / 256, 256>>>(cb, out_cb, out_nn, out_cc);
}

// round 17
// speedup vs baseline: 1.9794x; 1.0205x over previous
#include <cuda_runtime.h>
#include <math.h>
#include <stdint.h>

#define NROWS 32768
#define DDIM  1024
#define PDIM  256
#define NSEC  4
#define NCODE 1024
#define SECD  64

// ---------------- scratch (device globals, no allocation) ----------------
__device__ float g_P[NROWS * PDIM];         // projected  [N,P]
__device__ float g_Q[NROWS * PDIM];         // straight-through quantized [N,P]
__device__ float g_rowsum[NROWS];           // per-row squared recon error
__device__ float g_cov[PDIM * PDIM];        // P^T P accumulator
__device__ float g_cnorm[NSEC * NCODE];     // |c|^2 per code
__device__ float g_sx[NSEC * NROWS];        // |x_sec|^2 per (sec,row)
__device__ unsigned long long g_amin[NSEC * NROWS];  // packed (key, idx)
__device__ float g_l2sum;
__device__ float g_covsum;
__device__ float g_pca_loss;

__device__ __forceinline__ unsigned int fkey(float f) {
    unsigned int u = __float_as_uint(f);
    return (u & 0x80000000u) ? ~u : (u | 0x80000000u);
}

// ---------------- init ----------------
__global__ void k_zero() {
    int i = blockIdx.x * blockDim.x + threadIdx.x;
    if (i < PDIM * PDIM)  g_cov[i] = 0.0f;
    if (i < NROWS)        g_rowsum[i] = 0.0f;
    if (i == 0) { g_l2sum = 0.0f; g_covsum = 0.0f; }
}

// |c|^2 — 8 accumulators (k mod 8) + pairwise tree (SACRED chain)
__global__ void k_cnorm(const float* __restrict__ cb) {
    int w = blockIdx.x * blockDim.x + threadIdx.x;
    if (w >= NSEC * NCODE) return;
    const float* p = cb + (size_t)w * SECD;
    float a[8] = {};
    for (int k = 0; k < SECD; k += 8) {
        float4 v0 = *(const float4*)(p + k);
        float4 v1 = *(const float4*)(p + k + 4);
        a[0] = __fadd_rn(a[0], __fmul_rn(v0.x, v0.x));
        a[1] = __fadd_rn(a[1], __fmul_rn(v0.y, v0.y));
        a[2] = __fadd_rn(a[2], __fmul_rn(v0.z, v0.z));
        a[3] = __fadd_rn(a[3], __fmul_rn(v0.w, v0.w));
        a[4] = __fadd_rn(a[4], __fmul_rn(v1.x, v1.x));
        a[5] = __fadd_rn(a[5], __fmul_rn(v1.y, v1.y));
        a[6] = __fadd_rn(a[6], __fmul_rn(v1.z, v1.z));
        a[7] = __fadd_rn(a[7], __fmul_rn(v1.w, v1.w));
    }
    float s01 = __fadd_rn(a[0], a[1]), s23 = __fadd_rn(a[2], a[3]);
    float s45 = __fadd_rn(a[4], a[5]), s67 = __fadd_rn(a[6], a[7]);
    g_cnorm[w] = __fadd_rn(__fadd_rn(s01, s23), __fadd_rn(s45, s67));
}

// |x_sec|^2 — 8 accumulators + pairwise tree (SACRED chain)
__global__ void k_sumx2() {
    int e = blockIdx.x * blockDim.x + threadIdx.x;
    if (e >= NSEC * NROWS) return;
    int s = e >> 15;
    int r = e & (NROWS - 1);
    const float* x = g_P + (size_t)r * PDIM + s * SECD;
    float a[8] = {};
    for (int k = 0; k < SECD; k += 8) {
        float4 v0 = *(const float4*)(x + k);
        float4 v1 = *(const float4*)(x + k + 4);
        a[0] = __fadd_rn(a[0], __fmul_rn(v0.x, v0.x));
        a[1] = __fadd_rn(a[1], __fmul_rn(v0.y, v0.y));
        a[2] = __fadd_rn(a[2], __fmul_rn(v0.z, v0.z));
        a[3] = __fadd_rn(a[3], __fmul_rn(v0.w, v0.w));
        a[4] = __fadd_rn(a[4], __fmul_rn(v1.x, v1.x));
        a[5] = __fadd_rn(a[5], __fmul_rn(v1.y, v1.y));
        a[6] = __fadd_rn(a[6], __fmul_rn(v1.z, v1.z));
        a[7] = __fadd_rn(a[7], __fmul_rn(v1.w, v1.w));
    }
    float s01 = __fadd_rn(a[0], a[1]), s23 = __fadd_rn(a[2], a[3]);
    float s45 = __fadd_rn(a[4], a[5]), s67 = __fadd_rn(a[6], a[7]);
    g_sx[e] = __fadd_rn(__fadd_rn(s01, s23), __fadd_rn(s45, s67));
}

// ====== GEMM 1: P = (X + bias) @ W — 128x128 tile, 8x8 microtile ======
__global__ __launch_bounds__(256) void k_gemm_proj(
    const float* __restrict__ X, const float* __restrict__ W,
    const float* __restrict__ bias) {
    __shared__ float As[16][128];
    __shared__ float Bs[16][128];
    const int m0 = blockIdx.y * 128, n0 = blockIdx.x * 128;
    const int tid = threadIdx.x;
    const int ty = tid >> 4, tx = tid & 15;
    float acc[2][2][4][4] = {};
    for (int k0 = 0; k0 < DDIM; k0 += 16) {
        #pragma unroll
        for (int q = 0; q < 2; q++) {
            int t = tid * 2 + q;
            int r = t >> 2, cg = (t & 3) * 4;
            float4 a = *(const float4*)(X + (size_t)(m0 + r) * DDIM + k0 + cg);
            float4 pb = *(const float4*)(bias + k0 + cg);
            As[cg + 0][r] = __fadd_rn(a.x, pb.x);
            As[cg + 1][r] = __fadd_rn(a.y, pb.y);
            As[cg + 2][r] = __fadd_rn(a.z, pb.z);
            As[cg + 3][r] = __fadd_rn(a.w, pb.w);
        }
        #pragma unroll
        for (int q = 0; q < 2; q++) {
            int t = tid * 2 + q;
            int r = t >> 5, cg = (t & 31) * 4;
            *(float4*)&Bs[r][cg] =
                *(const float4*)(W + (size_t)(k0 + r) * PDIM + n0 + cg);
        }
        __syncthreads();
        #pragma unroll
        for (int k = 0; k < 16; k++) {
            float4 ra0 = *(const float4*)&As[k][ty * 4];
            float4 ra1 = *(const float4*)&As[k][64 + ty * 4];
            float4 rb0 = *(const float4*)&Bs[k][tx * 4];
            float4 rb1 = *(const float4*)&Bs[k][64 + tx * 4];
            float aa[2][4] = {{ra0.x, ra0.y, ra0.z, ra0.w},
                              {ra1.x, ra1.y, ra1.z, ra1.w}};
            float bb[2][4] = {{rb0.x, rb0.y, rb0.z, rb0.w},
                              {rb1.x, rb1.y, rb1.z, rb1.w}};
            #pragma unroll
            for (int p = 0; p < 2; p++)
                #pragma unroll
                for (int q2 = 0; q2 < 2; q2++)
                    #pragma unroll
                    for (int i = 0; i < 4; i++)
                        #pragma unroll
                        for (int j = 0; j < 4; j++)
                            acc[p][q2][i][j] =
                                __fmaf_rn(aa[p][i], bb[q2][j], acc[p][q2][i][j]);
        }
        __syncthreads();
    }
    #pragma unroll
    for (int p = 0; p < 2; p++)
        #pragma unroll
        for (int i = 0; i < 4; i++) {
            int row = m0 + p * 64 + ty * 4 + i;
            #pragma unroll
            for (int q2 = 0; q2 < 2; q2++) {
                float4 v = make_float4(acc[p][q2][i][0], acc[p][q2][i][1],
                                       acc[p][q2][i][2], acc[p][q2][i][3]);
                *(float4*)(g_P + (size_t)row * PDIM + n0 + q2 * 64 + tx * 4) = v;
            }
        }
}

// == GEMM 2 (fused): U = P@W^T - bias; accumulate ||X-U||^2 — 128x128 tile ==
__global__ __launch_bounds__(256) void k_gemm_recon(
    const float* __restrict__ X, const float* __restrict__ W,
    const float* __restrict__ bias) {
    __shared__ float As[16][128];
    __shared__ float Bs[16][128];
    __shared__ float red[128][17];
    const int m0 = blockIdx.y * 128, d0 = blockIdx.x * 128;
    const int tid = threadIdx.x;
    const int ty = tid >> 4, tx = tid & 15;
    float acc[2][2][4][4] = {};
    for (int k0 = 0; k0 < PDIM; k0 += 16) {
        #pragma unroll
        for (int q = 0; q < 2; q++) {
            int t = tid * 2 + q;
            int r = t >> 2, cg = (t & 3) * 4;
            float4 a = *(const float4*)(g_P + (size_t)(m0 + r) * PDIM + k0 + cg);
            As[cg + 0][r] = a.x;
            As[cg + 1][r] = a.y;
            As[cg + 2][r] = a.z;
            As[cg + 3][r] = a.w;
            float4 b = *(const float4*)(W + (size_t)(d0 + r) * PDIM + k0 + cg);
            Bs[cg + 0][r] = b.x;
            Bs[cg + 1][r] = b.y;
            Bs[cg + 2][r] = b.z;
            Bs[cg + 3][r] = b.w;
        }
        __syncthreads();
        #pragma unroll
        for (int k = 0; k < 16; k++) {
            float4 ra0 = *(const float4*)&As[k][ty * 4];
            float4 ra1 = *(const float4*)&As[k][64 + ty * 4];
            float4 rb0 = *(const float4*)&Bs[k][tx * 4];
            float4 rb1 = *(const float4*)&Bs[k][64 + tx * 4];
            float aa[2][4] = {{ra0.x, ra0.y, ra0.z, ra0.w},
                              {ra1.x, ra1.y, ra1.z, ra1.w}};
            float bb[2][4] = {{rb0.x, rb0.y, rb0.z, rb0.w},
                              {rb1.x, rb1.y, rb1.z, rb1.w}};
            #pragma unroll
            for (int p = 0; p < 2; p++)
                #pragma unroll
                for (int q2 = 0; q2 < 2; q2++)
                    #pragma unroll
                    for (int i = 0; i < 4; i++)
                        #pragma unroll
                        for (int j = 0; j < 4; j++)
                            acc[p][q2][i][j] =
                                __fmaf_rn(aa[p][i], bb[q2][j], acc[p][q2][i][j]);
        }
        __syncthreads();
    }
    #pragma unroll
    for (int p = 0; p < 2; p++)
        #pragma unroll
        for (int i = 0; i < 4; i++) {
            int rl = p * 64 + ty * 4 + i;
            int row = m0 + rl;
            float part = 0.0f;
            #pragma unroll
            for (int q2 = 0; q2 < 2; q2++) {
                int dg = d0 + q2 * 64 + tx * 4;
                float4 b4 = *(const float4*)(bias + dg);
                float4 x4 = *(const float4*)(X + (size_t)row * DDIM + dg);
                float bb[4] = {b4.x, b4.y, b4.z, b4.w};
                float xx[4] = {x4.x, x4.y, x4.z, x4.w};
                #pragma unroll
                for (int j = 0; j < 4; j++) {
                    float diff = xx[j] - (acc[p][q2][i][j] - bb[j]);
                    part += diff * diff;
                }
            }
            red[rl][tx] = part;
        }
    __syncthreads();
    if (tid < 128) {
        float s = 0.0f;
        #pragma unroll
        for (int x = 0; x < 16; x++) s += red[tid][x];
        atomicAdd(&g_rowsum[m0 + tid], s);
    }
}

// ---------------- cov = P^T @ P (split-K, atomic accumulate) ----------------
__global__ __launch_bounds__(256) void k_cov() {
    __shared__ float Ai[16][64];
    __shared__ float Aj[16][64];
    const int i0 = blockIdx.x * 64, j0 = blockIdx.y * 64;
    const int mbase = blockIdx.z * 2048;
    const int tid = threadIdx.x;
    const int ty = tid >> 4, tx = tid & 15;
    const int mrow = tid >> 4, cg = (tid & 15) * 4;
    float acc[4][4] = {};
    for (int m0 = mbase; m0 < mbase + 2048; m0 += 16) {
        *(float4*)&Ai[mrow][cg] = *(const float4*)(g_P + (size_t)(m0 + mrow) * PDIM + i0 + cg);
        *(float4*)&Aj[mrow][cg] = *(const float4*)(g_P + (size_t)(m0 + mrow) * PDIM + j0 + cg);
        __syncthreads();
        #pragma unroll
        for (int k = 0; k < 16; k++) {
            float4 ra = *(const float4*)&Ai[k][ty * 4];
            float4 rb = *(const float4*)&Aj[k][tx * 4];
            float aa[4] = {ra.x, ra.y, ra.z, ra.w};
            float bb[4] = {rb.x, rb.y, rb.z, rb.w};
            #pragma unroll
            for (int i = 0; i < 4; i++)
                #pragma unroll
                for (int j = 0; j < 4; j++)
                    acc[i][j] = __fmaf_rn(aa[i], bb[j], acc[i][j]);
        }
        __syncthreads();
    }
    #pragma unroll
    for (int i = 0; i < 4; i++)
        #pragma unroll
        for (int j = 0; j < 4; j++)
            atomicAdd(&g_cov[(size_t)(i0 + ty * 4 + i) * PDIM + j0 + tx * 4 + j], acc[i][j]);
}

// ---------------- loss reductions ----------------
__global__ void k_l2reduce() {
    int i = blockIdx.x * blockDim.x + threadIdx.x;
    float v = (i < NROWS) ? sqrtf(g_rowsum[i]) : 0.0f;
    #pragma unroll
    for (int o = 16; o > 0; o >>= 1) v += __shfl_down_sync(0xFFFFFFFFu, v, o);
    __shared__ float w[8];
    if ((threadIdx.x & 31) == 0) w[threadIdx.x >> 5] = v;
    __syncthreads();
    if (threadIdx.x == 0) {
        float s = 0.0f;
        for (int q = 0; q < 8; q++) s += w[q];
        atomicAdd(&g_l2sum, s);
    }
}

__global__ void k_covloss() {
    int i = blockIdx.x * blockDim.x + threadIdx.x;
    float v = 0.0f;
    if (i < PDIM * PDIM) {
        int r = i >> 8, c = i & 255;
        v = g_cov[i] * (1.0f / NROWS) - (r == c ? 1.0f : 0.0f);
        v = v * v;
    }
    #pragma unroll
    for (int o = 16; o > 0; o >>= 1) v += __shfl_down_sync(0xFFFFFFFFu, v, o);
    __shared__ float w[8];
    if ((threadIdx.x & 31) == 0) w[threadIdx.x >> 5] = v;
    __syncthreads();
    if (threadIdx.x == 0) {
        float s = 0.0f;
        for (int q = 0; q < 8; q++) s += w[q];
        atomicAdd(&g_covsum, s);
    }
}

__global__ void k_finalize() {
    g_pca_loss = g_l2sum * (1.0f / NROWS) + g_covsum * (1.0f / (PDIM * PDIM));
}

// ====== VQ scores + argmin — 64 rows x ALL 1024 codes per block ======
// SACRED per-element chain: 4 accumulators (k mod 4), ascending k,
// combine rn(rn(a0+a1)+rn(a2+a3)); d = rn(rn(sx-2t)+cn); LOW-index ties via
// packed (key<<32|idx) min (order-independent). Microtile 4 rows x 8 codes.
__global__ __launch_bounds__(256, 1) void k_vqscore(const float* __restrict__ cb) {
    __shared__ float smemf[64 * 64 + 64 * 128];   // As | Bs = 48KB
    float* As = smemf;            // As[k*64 + row], k 0..63, row 0..63
    float* Bs = smemf + 64 * 64;  // Bs[k*128 + code], k 0..63, code 0..127
    const int s = blockIdx.y;
    const int m0 = blockIdx.x * 64;
    const int tid = threadIdx.x;
    const int ty = tid >> 4, tx = tid & 15;
    const float* cbs = cb + (size_t)s * NCODE * SECD;

    // load A tile once: As[k][row] = P[m0+row][s*64+k]
    {
        int row = tid >> 2, kq = (tid & 3) * 16;
        #pragma unroll
        for (int u = 0; u < 4; u++) {
            int k = kq + u * 4;
            float4 a = *(const float4*)(g_P + (size_t)(m0 + row) * PDIM + s * SECD + k);
            As[(k + 0) * 64 + row] = a.x;
            As[(k + 1) * 64 + row] = a.y;
            As[(k + 2) * 64 + row] = a.z;
            As[(k + 3) * 64 + row] = a.w;
        }
    }

    float sx[4];
    #pragma unroll
    for (int i = 0; i < 4; i++) sx[i] = g_sx[s * NROWS + m0 + ty * 4 + i];

    unsigned long long best[4] = {0xFFFFFFFFFFFFFFFFull, 0xFFFFFFFFFFFFFFFFull,
                                  0xFFFFFFFFFFFFFFFFull, 0xFFFFFFFFFFFFFFFFull};

    for (int citer = 0; citer < 8; citer++) {
        const int c0 = citer * 128;
        __syncthreads();   // protect Bs (and As on first iter) before overwrite
        // load B tile: Bs[k][code] = cb[c0+code][k]
        {
            int code = tid & 127, half = (tid >> 7) * 32;
            #pragma unroll
            for (int u = 0; u < 8; u++) {
                int k = half + u * 4;
                float4 b = *(const float4*)(cbs + (size_t)(c0 + code) * SECD + k);
                Bs[(k + 0) * 128 + code] = b.x;
                Bs[(k + 1) * 128 + code] = b.y;
                Bs[(k + 2) * 128 + code] = b.z;
                Bs[(k + 3) * 128 + code] = b.w;
            }
        }
        __syncthreads();

        float acc[4][2][4][4] = {};   // [chain][quadrant][row_i][code_j]
        #pragma unroll 2
        for (int k16 = 0; k16 < 16; k16++) {
            #pragma unroll
            for (int c = 0; c < 4; c++) {
                int k = k16 * 4 + c;
                float4 ra = *(const float4*)&As[k * 64 + ty * 4];
                float4 rb0 = *(const float4*)&Bs[k * 128 + tx * 4];
                float4 rb1 = *(const float4*)&Bs[k * 128 + 64 + tx * 4];
                float aa[4] = {ra.x, ra.y, ra.z, ra.w};
                float bb[2][4] = {{rb0.x, rb0.y, rb0.z, rb0.w},
                                  {rb1.x, rb1.y, rb1.z, rb1.w}};
                #pragma unroll
                for (int q = 0; q < 2; q++)
                    #pragma unroll
                    for (int i = 0; i < 4; i++)
                        #pragma unroll
                        for (int j = 0; j < 4; j++)
                            acc[c][q][i][j] =
                                __fmaf_rn(aa[i], bb[q][j], acc[c][q][i][j]);
            }
        }
        // epilogue: combine chains, score, update running best
        #pragma unroll
        for (int q = 0; q < 2; q++) {
            float cn[4];
            #pragma unroll
            for (int j = 0; j < 4; j++)
                cn[j] = g_cnorm[s * NCODE + c0 + q * 64 + tx * 4 + j];
            #pragma unroll
            for (int i = 0; i < 4; i++)
                #pragma unroll
                for (int j = 0; j < 4; j++) {
                    float t = __fadd_rn(__fadd_rn(acc[0][q][i][j], acc[1][q][i][j]),
                                        __fadd_rn(acc[2][q][i][j], acc[3][q][i][j]));
                    float sc = __fadd_rn(__fsub_rn(sx[i], __fmul_rn(2.0f, t)), cn[j]);
                    unsigned long long p =
                        ((unsigned long long)fkey(sc) << 32)
                        | (unsigned)(c0 + q * 64 + tx * 4 + j);
                    if (p < best[i]) best[i] = p;
                }
        }
    }
    __syncthreads();
    // cross-tx reduction: alias red over As region (done with As)
    unsigned long long* red = (unsigned long long*)smemf;  // red[row*17 + tx]
    #pragma unroll
    for (int i = 0; i < 4; i++) red[(ty * 4 + i) * 17 + tx] = best[i];
    __syncthreads();
    if (tid < 64) {
        unsigned long long b = red[tid * 17];
        #pragma unroll
        for (int x = 1; x < 16; x++) {
            unsigned long long v = red[tid * 17 + x];
            if (v < b) b = v;
        }
        g_amin[(size_t)s * NROWS + m0 + tid] = b;   // single writer, no atomic
    }
}

// ------- gather quantized sections with straight-through rounding -------
__global__ void k_gather(const float* __restrict__ cb) {
    int e = blockIdx.x * blockDim.x + threadIdx.x;
    int n = e >> 8, p = e & 255, s = p >> 6, j = p & 63;
    int idx = (int)(unsigned)(g_amin[(size_t)s * NROWS + n] & 0xFFFFFFFFull);
    float q = cb[(size_t)s * NCODE * SECD + (size_t)idx * SECD + j];
    float x = g_P[e];
    g_Q[e] = __fadd_rn(x, __fsub_rn(q, x));
}

// ====== GEMM 5: out = Q_st @ W^T - bias — 128x128 tile, 8x8 microtile ======
__global__ __launch_bounds__(256) void k_gemm_out(
    const float* __restrict__ W, const float* __restrict__ bias,
    float* __restrict__ out) {
    __shared__ float As[16][128];
    __shared__ float Bs[16][128];
    const int m0 = blockIdx.y * 128, d0 = blockIdx.x * 128;
    const int tid = threadIdx.x;
    const int ty = tid >> 4, tx = tid & 15;
    float acc[2][2][4][4] = {};
    for (int k0 = 0; k0 < PDIM; k0 += 16) {
        #pragma unroll
        for (int q = 0; q < 2; q++) {
            int t = tid * 2 + q;
            int r = t >> 2, cg = (t & 3) * 4;
            float4 a = *(const float4*)(g_Q + (size_t)(m0 + r) * PDIM + k0 + cg);
            As[cg + 0][r] = a.x;
            As[cg + 1][r] = a.y;
            As[cg + 2][r] = a.z;
            As[cg + 3][r] = a.w;
            float4 b = *(const float4*)(W + (size_t)(d0 + r) * PDIM + k0 + cg);
            Bs[cg + 0][r] = b.x;
            Bs[cg + 1][r] = b.y;
            Bs[cg + 2][r] = b.z;
            Bs[cg + 3][r] = b.w;
        }
        __syncthreads();
        #pragma unroll
        for (int k = 0; k < 16; k++) {
            float4 ra0 = *(const float4*)&As[k][ty * 4];
            float4 ra1 = *(const float4*)&As[k][64 + ty * 4];
            float4 rb0 = *(const float4*)&Bs[k][tx * 4];
            float4 rb1 = *(const float4*)&Bs[k][64 + tx * 4];
            float aa[2][4] = {{ra0.x, ra0.y, ra0.z, ra0.w},
                              {ra1.x, ra1.y, ra1.z, ra1.w}};
            float bb[2][4] = {{rb0.x, rb0.y, rb0.z, rb0.w},
                              {rb1.x, rb1.y, rb1.z, rb1.w}};
            #pragma unroll
            for (int p = 0; p < 2; p++)
                #pragma unroll
                for (int q2 = 0; q2 < 2; q2++)
                    #pragma unroll
                    for (int i = 0; i < 4; i++)
                        #pragma unroll
                        for (int j = 0; j < 4; j++)
                            acc[p][q2][i][j] =
                                __fmaf_rn(aa[p][i], bb[q2][j], acc[p][q2][i][j]);
        }
        __syncthreads();
    }
    #pragma unroll
    for (int p = 0; p < 2; p++)
        #pragma unroll
        for (int i = 0; i < 4; i++) {
            int row = m0 + p * 64 + ty * 4 + i;
            #pragma unroll
            for (int q2 = 0; q2 < 2; q2++) {
                int dg = d0 + q2 * 64 + tx * 4;
                float4 b4 = *(const float4*)(bias + dg);
                float4 v = make_float4(acc[p][q2][i][0] - b4.x,
                                       acc[p][q2][i][1] - b4.y,
                                       acc[p][q2][i][2] - b4.z,
                                       acc[p][q2][i][3] - b4.w);
                *(float4*)(out + (size_t)row * DDIM + dg) = v;
            }
        }
}

// ------------- quantization loss (raw q vs fp32 P) -------------
__global__ void k_qloss(const float* __restrict__ cb, float* __restrict__ out_ql) {
    int e = blockIdx.x * blockDim.x + threadIdx.x;
    int n = e >> 6, j = e & 63;
    float sum = 0.0f;
    #pragma unroll
    for (int s = 0; s < NSEC; s++) {
        int idx = (int)(unsigned)(g_amin[(size_t)s * NROWS + n] & 0xFFFFFFFFull);
        float q = cb[(size_t)s * NCODE * SECD + (size_t)idx * SECD + j];
        float x = g_P[(size_t)n * PDIM + s * SECD + j];
        float d = __fsub_rn(q, x);
        sum += d * d;
    }
    out_ql[e] = 0.25f * sum + g_pca_loss;
}

// ---------------- misc outputs ----------------
__global__ void k_misc(const float* __restrict__ cb, float* __restrict__ out_cb,
                       float* __restrict__ out_nn, float* __restrict__ out_cc) {
    int e = blockIdx.x * blockDim.x + threadIdx.x;
    if (e < NSEC * NCODE * SECD) out_cb[e] = cb[e];
    if (e < NSEC * NROWS)
        out_nn[e] = (float)(unsigned)(g_amin[e] & 0xFFFFFFFFull);
    if (e < NSEC * NCODE) out_cc[e] = 1.0f;
}

// ---------------- launcher ----------------
extern "C" void kernel_launch(void* const* d_in, const int* in_sizes, int n_in,
                              void* d_out, int out_size) {
    const float* X    = (const float*)d_in[0];
    const float* W    = (const float*)d_in[1];
    const float* bias = (const float*)d_in[2];
    const float* cb   = (const float*)d_in[3];
    float* out = (float*)d_out;

    float* out_q  = out;                          // 33554432
    float* out_ql = out_q + 33554432;             // 2097152
    float* out_nn = out_ql + 2097152;             // 131072
    float* out_cb = out_nn + 131072;              // 262144
    float* out_cc = out_cb + 262144;              // 4096

    k_zero<<<512, 256>>>();
    k_cnorm<<<NSEC * NCODE / 256, 256>>>(cb);
    k_gemm_proj<<<dim3(PDIM / 128, NROWS / 128), 256>>>(X, W, bias);
    k_sumx2<<<NSEC * NROWS / 256, 256>>>();
    k_gemm_recon<<<dim3(DDIM / 128, NROWS / 128), 256>>>(X, W, bias);
    k_cov<<<dim3(4, 4, 16), 256>>>();
    k_l2reduce<<<NROWS / 256, 256>>>();
    k_covloss<<<PDIM * PDIM / 256, 256>>>();
    k_finalize<<<1, 1>>>();
    k_vqscore<<<dim3(NROWS / 64, NSEC), 256>>>(cb);
    k_gather<<<NROWS * PDIM / 256, 256>>>(cb);
    k_gemm_out<<<dim3(DDIM / 128, NROWS / 128), 256>>>(W, bias, out_q);
    k_qloss<<<NROWS * SECD / 256, 256>>>(cb, out_ql);
    k_misc<<<NSEC * NCODE * SECD / 256, 256>>>(cb, out_cb, out_nn, out_cc);
}